// round 7
// baseline (speedup 1.0000x reference)
#include <cuda_runtime.h>
#include <cuda_bf16.h>
#include <cuda_fp16.h>
#include <cstdint>

#define D 128
#define OUTD 128
#define MAXN 100000
#define EPS 0.1f
#define CAP 48   // per-dst bucket capacity (avg in-degree 6.4)

// Scratch (allocation-free rule: __device__ globals)
__device__ float   g_agg[(size_t)MAXN * D];
__device__ __half  g_x_h[(size_t)MAXN * D];
__device__ float   g_alpha_l[MAXN];
__device__ float   g_alpha_r[MAXN];
__device__ int     g_is64;
__device__ uint32_t g_W_hi[128 * 64];   // bf16x2 packed, [n][k/2]
__device__ uint32_t g_W_lo[128 * 64];
__device__ int     g_cnt[MAXN];
__device__ uint2   g_bucket[(size_t)MAXN * CAP];  // (src, coeff bits)

// ---------------------------------------------------------------------------
// Kernel P: fused prep. blocks [0,32): W -> bf16 hi/lo; [32, 32+NZ): zero cnt;
// last block: int64/int32 detect.
// ---------------------------------------------------------------------------
__global__ void prep_kernel(const float* __restrict__ W,
                            const unsigned int* __restrict__ ei_words,
                            int N, int E, int nzero) {
    int b = blockIdx.x;
    if (b < 32) {
        int idx = b * 256 + threadIdx.x;  // < 8192
        int n = idx >> 6, k2 = idx & 63;
        float w0 = W[n * D + 2 * k2];
        float w1 = W[n * D + 2 * k2 + 1];
        __nv_bfloat16 h0 = __float2bfloat16_rn(w0);
        __nv_bfloat16 h1 = __float2bfloat16_rn(w1);
        float l0 = w0 - __bfloat162float(h0);
        float l1 = w1 - __bfloat162float(h1);
        __nv_bfloat162 hp = __halves2bfloat162(h0, h1);
        __nv_bfloat162 lp = __halves2bfloat162(__float2bfloat16_rn(l0),
                                               __float2bfloat16_rn(l1));
        g_W_hi[idx] = *reinterpret_cast<uint32_t*>(&hp);
        g_W_lo[idx] = *reinterpret_cast<uint32_t*>(&lp);
    } else if (b < 32 + nzero) {
        int i = (b - 32) * 256 + threadIdx.x;
        if (i < N) g_cnt[i] = 0;
    } else {
        __shared__ int bad;
        if (threadIdx.x == 0) bad = 0;
        __syncthreads();
        int nchk = E < 1024 ? E : 1024;
        for (int k = threadIdx.x; k < nchk; k += blockDim.x)
            if (ei_words[2 * k + 1] != 0u) bad = 1;
        __syncthreads();
        if (threadIdx.x == 0) g_is64 = bad ? 0 : 1;
    }
}

// ---------------------------------------------------------------------------
// Kernel 1: alpha logits + agg = EPS*x_0 + write fp16 copy of x
// ---------------------------------------------------------------------------
__global__ void alpha_init_kernel(const float* __restrict__ x,
                                  const float* __restrict__ x0,
                                  const float* __restrict__ att_l,
                                  const float* __restrict__ att_r,
                                  int N) {
    int warp = (blockIdx.x * blockDim.x + threadIdx.x) >> 5;
    int lane = threadIdx.x & 31;
    if (warp >= N) return;

    float4 xv = reinterpret_cast<const float4*>(x + (size_t)warp * D)[lane];
    float4 al = reinterpret_cast<const float4*>(att_l)[lane];
    float4 ar = reinterpret_cast<const float4*>(att_r)[lane];

    float sl = xv.x * al.x + xv.y * al.y + xv.z * al.z + xv.w * al.w;
    float sr = xv.x * ar.x + xv.y * ar.y + xv.z * ar.z + xv.w * ar.w;
#pragma unroll
    for (int o = 16; o > 0; o >>= 1) {
        sl += __shfl_xor_sync(0xffffffffu, sl, o);
        sr += __shfl_xor_sync(0xffffffffu, sr, o);
    }
    if (lane == 0) {
        g_alpha_l[warp] = sl;
        g_alpha_r[warp] = sr;
    }

    __half2 h01 = __floats2half2_rn(xv.x, xv.y);
    __half2 h23 = __floats2half2_rn(xv.z, xv.w);
    uint2 hw = make_uint2(*reinterpret_cast<uint32_t*>(&h01),
                          *reinterpret_cast<uint32_t*>(&h23));
    reinterpret_cast<uint2*>(g_x_h + (size_t)warp * D)[lane] = hw;

    float4 x0v = reinterpret_cast<const float4*>(x0 + (size_t)warp * D)[lane];
    float4 outv = make_float4(EPS * x0v.x, EPS * x0v.y, EPS * x0v.z, EPS * x0v.w);
    reinterpret_cast<float4*>(g_agg + (size_t)warp * D)[lane] = outv;
}

// ---------------------------------------------------------------------------
// Kernel 2a: fill per-dst buckets with (src, coeff). Thread per edge.
// ---------------------------------------------------------------------------
__global__ void fill_kernel(const float* __restrict__ x,
                            const void* __restrict__ ei_raw,
                            const float* __restrict__ ew,
                            int E) {
    int e = blockIdx.x * blockDim.x + threadIdx.x;
    if (e >= E) return;

    int src, dst;
    if (g_is64) {
        const long long* ei = (const long long*)ei_raw;
        src = (int)ei[e];
        dst = (int)ei[(size_t)E + e];
    } else {
        const int* ei = (const int*)ei_raw;
        src = ei[e];
        dst = ei[(size_t)E + e];
    }
    float c = tanhf(g_alpha_l[src] + g_alpha_r[dst]) * ew[e];

    int slot = atomicAdd(&g_cnt[dst], 1);
    if (slot < CAP) {
        g_bucket[(size_t)dst * CAP + slot] = make_uint2((unsigned)src, __float_as_uint(c));
    } else {
        // essentially-never fallback: direct fp32 atomic add of c * x[src]
        const float4* xr = reinterpret_cast<const float4*>(x + (size_t)src * D);
        float* p = g_agg + (size_t)dst * D;
        for (int i = 0; i < 32; i++) {
            float4 v = xr[i];
            asm volatile("red.global.add.v4.f32 [%0], {%1, %2, %3, %4};"
                         :: "l"(p + i * 4), "f"(v.x * c), "f"(v.y * c),
                            "f"(v.z * c), "f"(v.w * c)
                         : "memory");
        }
    }
}

// ---------------------------------------------------------------------------
// Kernel 2b: pull. Warp per dst node. Bucket entries read in ONE coalesced
// round (lanes 0..cnt-1), broadcast via shfl; fp16 gathers batched 8-deep
// for MLP; single red.global.add.v4 per lane into agg.
// ---------------------------------------------------------------------------
__global__ void pull_kernel(int N) {
    int node = (blockIdx.x * blockDim.x + threadIdx.x) >> 5;
    int lane = threadIdx.x & 31;
    if (node >= N) return;

    int cnt = g_cnt[node];
    if (cnt > CAP) cnt = CAP;
    if (cnt == 0) return;

    const uint2* b = g_bucket + (size_t)node * CAP;
    uint2 e0 = make_uint2(0u, 0u), e1 = make_uint2(0u, 0u);
    if (lane < cnt) e0 = b[lane];
    if (32 + lane < cnt) e1 = b[32 + lane];

    float ax = 0.f, ay = 0.f, az = 0.f, aw = 0.f;

    for (int j0 = 0; j0 < cnt; j0 += 8) {
        uint2 hw[8];
        float cs[8];
        // issue all 8 gathers before consuming any (MLP=8)
#pragma unroll
        for (int jj = 0; jj < 8; jj++) {
            int j = j0 + jj;                      // warp-uniform
            unsigned sx, cb;
            if (j < 32) {
                sx = __shfl_sync(0xffffffffu, e0.x, j);
                cb = __shfl_sync(0xffffffffu, e0.y, j);
            } else {
                sx = __shfl_sync(0xffffffffu, e1.x, j - 32);
                cb = __shfl_sync(0xffffffffu, e1.y, j - 32);
            }
            if (j < cnt) {
                hw[jj] = reinterpret_cast<const uint2*>(g_x_h + (size_t)sx * D)[lane];
                cs[jj] = __uint_as_float(cb);
            } else {
                hw[jj] = make_uint2(0u, 0u);
                cs[jj] = 0.f;
            }
        }
#pragma unroll
        for (int jj = 0; jj < 8; jj++) {
            float2 f01 = __half22float2(*reinterpret_cast<__half2*>(&hw[jj].x));
            float2 f23 = __half22float2(*reinterpret_cast<__half2*>(&hw[jj].y));
            ax = fmaf(cs[jj], f01.x, ax);
            ay = fmaf(cs[jj], f01.y, ay);
            az = fmaf(cs[jj], f23.x, az);
            aw = fmaf(cs[jj], f23.y, aw);
        }
    }

    float* p = g_agg + (size_t)node * D + lane * 4;
    asm volatile("red.global.add.v4.f32 [%0], {%1, %2, %3, %4};"
                 :: "l"(p), "f"(ax), "f"(ay), "f"(az), "f"(aw)
                 : "memory");
}

// ---------------------------------------------------------------------------
// Kernel 3: out = relu(agg) @ W^T + b via bf16x3 mma.m16n8k16, 2 CTAs/SM.
// ---------------------------------------------------------------------------
#define PITCH 68   // words per row (64 + 4 pad)

#define SM_WHI 0
#define SM_WLO (128 * PITCH)
#define SM_AHI (2 * 128 * PITCH)
#define SM_ALO (2 * 128 * PITCH + 64 * PITCH)
#define SM_WORDS (2 * 128 * PITCH + 2 * 64 * PITCH)

__device__ __forceinline__ void mma_bf16(float* d, const uint32_t* a, const uint32_t* b) {
    asm volatile(
        "mma.sync.aligned.m16n8k16.row.col.f32.bf16.bf16.f32 "
        "{%0,%1,%2,%3}, {%4,%5,%6,%7}, {%8,%9}, {%0,%1,%2,%3};"
        : "+f"(d[0]), "+f"(d[1]), "+f"(d[2]), "+f"(d[3])
        : "r"(a[0]), "r"(a[1]), "r"(a[2]), "r"(a[3]), "r"(b[0]), "r"(b[1]));
}

__global__ __launch_bounds__(256, 2)
void gemm_kernel(const float* __restrict__ bias,
                 float* __restrict__ out,
                 int N) {
    extern __shared__ uint32_t sm[];
    int tid = threadIdx.x;
    int lane = tid & 31;
    int wid = tid >> 5;
    int warpM = wid >> 2;
    int warpN = wid & 3;

    for (int i = tid; i < 128 * 16; i += 256) {
        int r = i >> 4;
        int c4 = i & 15;
        uint4 h = reinterpret_cast<const uint4*>(g_W_hi)[(size_t)r * 16 + c4];
        uint4 l = reinterpret_cast<const uint4*>(g_W_lo)[(size_t)r * 16 + c4];
        *reinterpret_cast<uint4*>(&sm[SM_WHI + r * PITCH + c4 * 4]) = h;
        *reinterpret_cast<uint4*>(&sm[SM_WLO + r * PITCH + c4 * 4]) = l;
    }

    float bv[4][2];
#pragma unroll
    for (int nt = 0; nt < 4; nt++) {
        int col = warpN * 32 + nt * 8 + (lane & 3) * 2;
        bv[nt][0] = bias[col];
        bv[nt][1] = bias[col + 1];
    }
    __syncthreads();

    int ntiles = (N + 63) >> 6;
    for (int t = blockIdx.x; t < ntiles; t += gridDim.x) {
        int m0 = t << 6;

        for (int i = tid; i < 64 * 32; i += 256) {
            int r = i >> 5;
            int c4 = i & 31;
            int row = m0 + r;
            float4 v;
            if (row < N)
                v = *reinterpret_cast<const float4*>(g_agg + (size_t)row * D + c4 * 4);
            else
                v = make_float4(0.f, 0.f, 0.f, 0.f);
            float a0 = fmaxf(v.x, 0.f), a1 = fmaxf(v.y, 0.f);
            float a2 = fmaxf(v.z, 0.f), a3 = fmaxf(v.w, 0.f);
            __nv_bfloat16 h0 = __float2bfloat16_rn(a0);
            __nv_bfloat16 h1 = __float2bfloat16_rn(a1);
            __nv_bfloat16 h2 = __float2bfloat16_rn(a2);
            __nv_bfloat16 h3 = __float2bfloat16_rn(a3);
            __nv_bfloat162 hp0 = __halves2bfloat162(h0, h1);
            __nv_bfloat162 hp1 = __halves2bfloat162(h2, h3);
            __nv_bfloat162 lp0 = __halves2bfloat162(
                __float2bfloat16_rn(a0 - __bfloat162float(h0)),
                __float2bfloat16_rn(a1 - __bfloat162float(h1)));
            __nv_bfloat162 lp1 = __halves2bfloat162(
                __float2bfloat16_rn(a2 - __bfloat162float(h2)),
                __float2bfloat16_rn(a3 - __bfloat162float(h3)));
            uint2 hw = make_uint2(*reinterpret_cast<uint32_t*>(&hp0),
                                  *reinterpret_cast<uint32_t*>(&hp1));
            uint2 lw = make_uint2(*reinterpret_cast<uint32_t*>(&lp0),
                                  *reinterpret_cast<uint32_t*>(&lp1));
            *reinterpret_cast<uint2*>(&sm[SM_AHI + r * PITCH + c4 * 2]) = hw;
            *reinterpret_cast<uint2*>(&sm[SM_ALO + r * PITCH + c4 * 2]) = lw;
        }
        __syncthreads();

        float acc[2][4][4];
#pragma unroll
        for (int mt = 0; mt < 2; mt++)
#pragma unroll
            for (int nt = 0; nt < 4; nt++)
#pragma unroll
                for (int i = 0; i < 4; i++) acc[mt][nt][i] = 0.f;

#pragma unroll
        for (int ks = 0; ks < 8; ks++) {
            int w0 = ks * 8 + (lane & 3);
            uint32_t ahi[2][4], alo[2][4];
#pragma unroll
            for (int mt = 0; mt < 2; mt++) {
                int r = warpM * 32 + mt * 16 + (lane >> 2);
                ahi[mt][0] = sm[SM_AHI + r * PITCH + w0];
                ahi[mt][1] = sm[SM_AHI + (r + 8) * PITCH + w0];
                ahi[mt][2] = sm[SM_AHI + r * PITCH + w0 + 4];
                ahi[mt][3] = sm[SM_AHI + (r + 8) * PITCH + w0 + 4];
                alo[mt][0] = sm[SM_ALO + r * PITCH + w0];
                alo[mt][1] = sm[SM_ALO + (r + 8) * PITCH + w0];
                alo[mt][2] = sm[SM_ALO + r * PITCH + w0 + 4];
                alo[mt][3] = sm[SM_ALO + (r + 8) * PITCH + w0 + 4];
            }
            uint32_t bhi[4][2], blo[4][2];
#pragma unroll
            for (int nt = 0; nt < 4; nt++) {
                int n = warpN * 32 + nt * 8 + (lane >> 2);
                bhi[nt][0] = sm[SM_WHI + n * PITCH + w0];
                bhi[nt][1] = sm[SM_WHI + n * PITCH + w0 + 4];
                blo[nt][0] = sm[SM_WLO + n * PITCH + w0];
                blo[nt][1] = sm[SM_WLO + n * PITCH + w0 + 4];
            }
#pragma unroll
            for (int mt = 0; mt < 2; mt++)
#pragma unroll
                for (int nt = 0; nt < 4; nt++) {
                    mma_bf16(acc[mt][nt], ahi[mt], blo[nt]);
                    mma_bf16(acc[mt][nt], alo[mt], bhi[nt]);
                    mma_bf16(acc[mt][nt], ahi[mt], bhi[nt]);
                }
        }

#pragma unroll
        for (int mt = 0; mt < 2; mt++) {
            int r0 = m0 + warpM * 32 + mt * 16 + (lane >> 2);
#pragma unroll
            for (int nt = 0; nt < 4; nt++) {
                int col = warpN * 32 + nt * 8 + (lane & 3) * 2;
                if (r0 < N) {
                    float2 v = make_float2(acc[mt][nt][0] + bv[nt][0],
                                           acc[mt][nt][1] + bv[nt][1]);
                    *reinterpret_cast<float2*>(out + (size_t)r0 * OUTD + col) = v;
                }
                if (r0 + 8 < N) {
                    float2 v = make_float2(acc[mt][nt][2] + bv[nt][0],
                                           acc[mt][nt][3] + bv[nt][1]);
                    *reinterpret_cast<float2*>(out + (size_t)(r0 + 8) * OUTD + col) = v;
                }
            }
        }
        __syncthreads();
    }
}

// ---------------------------------------------------------------------------
// Launch
// ---------------------------------------------------------------------------
extern "C" void kernel_launch(void* const* d_in, const int* in_sizes, int n_in,
                              void* d_out, int out_size) {
    const float* x      = (const float*)d_in[0];
    const float* x0     = (const float*)d_in[1];
    const float* ew     = (const float*)d_in[2];
    const float* att_l  = (const float*)d_in[3];
    const float* att_r  = (const float*)d_in[4];
    const float* W      = (const float*)d_in[5];
    const float* bias   = (const float*)d_in[6];
    const void*  ei     = (const void*)d_in[7];
    float* out = (float*)d_out;

    int N = in_sizes[1] / D;
    int E = in_sizes[2];

    static bool attr_set = false;
    if (!attr_set) {
        cudaFuncSetAttribute(gemm_kernel,
                             cudaFuncAttributeMaxDynamicSharedMemorySize,
                             SM_WORDS * 4);
        attr_set = true;
    }

    int nzero = (N + 255) / 256;
    prep_kernel<<<32 + nzero + 1, 256>>>(W, (const unsigned int*)ei, N, E, nzero);
    {
        int blocks = (N + 7) / 8;
        alpha_init_kernel<<<blocks, 256>>>(x, x0, att_l, att_r, N);
    }
    fill_kernel<<<(E + 255) / 256, 256>>>(x, ei, ew, E);
    {
        int blocks = (N + 7) / 8;
        pull_kernel<<<blocks, 256>>>(N);
    }
    gemm_kernel<<<296, 256, SM_WORDS * 4>>>(bias, out, N);
}

// round 8
// speedup vs baseline: 1.0484x; 1.0484x over previous
#include <cuda_runtime.h>
#include <cuda_bf16.h>
#include <cuda_fp16.h>
#include <cstdint>

#define D 128
#define OUTD 128
#define MAXN 100000
#define EPS 0.1f
#define CAP 48        // per-dst bucket capacity (avg in-degree 6.4)
#define OVFCAP 262144 // overflow list capacity (correctness fallback)

// Scratch (allocation-free rule: __device__ globals)
__device__ float   g_agg[(size_t)MAXN * D];   // relu(EPS*x0 + sum) after pull
__device__ __half  g_x_h[(size_t)MAXN * D];
__device__ float   g_alpha_l[MAXN];
__device__ float   g_alpha_r[MAXN];
__device__ int     g_is64;
__device__ uint32_t g_W_hi[128 * 64];   // bf16x2 packed, [n][k/2]
__device__ uint32_t g_W_lo[128 * 64];
__device__ int     g_cnt[MAXN];
__device__ uint2   g_bucket[(size_t)MAXN * CAP];  // (src, coeff bits)
__device__ int     g_ovf_cnt;
__device__ uint4   g_ovf[OVFCAP];                 // (dst, src, coeff bits, 0)

// ---------------------------------------------------------------------------
// Kernel P: fused prep. blocks [0,32): W -> bf16 hi/lo; [32, 32+NZ): zero cnt;
// last block: int64/int32 detect + zero overflow counter.
// ---------------------------------------------------------------------------
__global__ void prep_kernel(const float* __restrict__ W,
                            const unsigned int* __restrict__ ei_words,
                            int N, int E, int nzero) {
    int b = blockIdx.x;
    if (b < 32) {
        int idx = b * 256 + threadIdx.x;  // < 8192
        int n = idx >> 6, k2 = idx & 63;
        float w0 = W[n * D + 2 * k2];
        float w1 = W[n * D + 2 * k2 + 1];
        __nv_bfloat16 h0 = __float2bfloat16_rn(w0);
        __nv_bfloat16 h1 = __float2bfloat16_rn(w1);
        float l0 = w0 - __bfloat162float(h0);
        float l1 = w1 - __bfloat162float(h1);
        __nv_bfloat162 hp = __halves2bfloat162(h0, h1);
        __nv_bfloat162 lp = __halves2bfloat162(__float2bfloat16_rn(l0),
                                               __float2bfloat16_rn(l1));
        g_W_hi[idx] = *reinterpret_cast<uint32_t*>(&hp);
        g_W_lo[idx] = *reinterpret_cast<uint32_t*>(&lp);
    } else if (b < 32 + nzero) {
        int i = (b - 32) * 256 + threadIdx.x;
        if (i < N) g_cnt[i] = 0;
    } else {
        __shared__ int bad;
        if (threadIdx.x == 0) { bad = 0; g_ovf_cnt = 0; }
        __syncthreads();
        int nchk = E < 1024 ? E : 1024;
        for (int k = threadIdx.x; k < nchk; k += blockDim.x)
            if (ei_words[2 * k + 1] != 0u) bad = 1;
        __syncthreads();
        if (threadIdx.x == 0) g_is64 = bad ? 0 : 1;
    }
}

// ---------------------------------------------------------------------------
// Kernel 1: alpha logits + fp16 copy of x (no agg init anymore)
// ---------------------------------------------------------------------------
__global__ void alpha_init_kernel(const float* __restrict__ x,
                                  const float* __restrict__ att_l,
                                  const float* __restrict__ att_r,
                                  int N) {
    int warp = (blockIdx.x * blockDim.x + threadIdx.x) >> 5;
    int lane = threadIdx.x & 31;
    if (warp >= N) return;

    float4 xv = reinterpret_cast<const float4*>(x + (size_t)warp * D)[lane];
    float4 al = reinterpret_cast<const float4*>(att_l)[lane];
    float4 ar = reinterpret_cast<const float4*>(att_r)[lane];

    float sl = xv.x * al.x + xv.y * al.y + xv.z * al.z + xv.w * al.w;
    float sr = xv.x * ar.x + xv.y * ar.y + xv.z * ar.z + xv.w * ar.w;
#pragma unroll
    for (int o = 16; o > 0; o >>= 1) {
        sl += __shfl_xor_sync(0xffffffffu, sl, o);
        sr += __shfl_xor_sync(0xffffffffu, sr, o);
    }
    if (lane == 0) {
        g_alpha_l[warp] = sl;
        g_alpha_r[warp] = sr;
    }

    __half2 h01 = __floats2half2_rn(xv.x, xv.y);
    __half2 h23 = __floats2half2_rn(xv.z, xv.w);
    uint2 hw = make_uint2(*reinterpret_cast<uint32_t*>(&h01),
                          *reinterpret_cast<uint32_t*>(&h23));
    reinterpret_cast<uint2*>(g_x_h + (size_t)warp * D)[lane] = hw;
}

// ---------------------------------------------------------------------------
// Kernel 2a: fill per-dst buckets with (src, coeff). Thread per edge.
// Overflow (slot >= CAP): append to global overflow list (handled in pull).
// ---------------------------------------------------------------------------
__global__ void fill_kernel(const void* __restrict__ ei_raw,
                            const float* __restrict__ ew,
                            int E) {
    int e = blockIdx.x * blockDim.x + threadIdx.x;
    if (e >= E) return;

    int src, dst;
    if (g_is64) {
        const long long* ei = (const long long*)ei_raw;
        src = (int)ei[e];
        dst = (int)ei[(size_t)E + e];
    } else {
        const int* ei = (const int*)ei_raw;
        src = ei[e];
        dst = ei[(size_t)E + e];
    }
    float c = tanhf(g_alpha_l[src] + g_alpha_r[dst]) * ew[e];

    int slot = atomicAdd(&g_cnt[dst], 1);
    if (slot < CAP) {
        g_bucket[(size_t)dst * CAP + slot] = make_uint2((unsigned)src, __float_as_uint(c));
    } else {
        int o = atomicAdd(&g_ovf_cnt, 1);
        if (o < OVFCAP)
            g_ovf[o] = make_uint4((unsigned)dst, (unsigned)src, __float_as_uint(c), 0u);
    }
}

// ---------------------------------------------------------------------------
// Kernel 2b: pull. Warp per dst node; fp16 gathers, fp32 accumulate.
// Final: agg[node] = relu(EPS*x0 + sum) via plain float4 store (node owned
// by exactly one warp -> no atomics). Overflowed nodes scan the global list.
// ---------------------------------------------------------------------------
__global__ void pull_kernel(const float* __restrict__ x0, int N) {
    int node = (blockIdx.x * blockDim.x + threadIdx.x) >> 5;
    int lane = threadIdx.x & 31;
    if (node >= N) return;

    int cntr = g_cnt[node];
    int cnt = cntr > CAP ? CAP : cntr;

    const uint2* b = g_bucket + (size_t)node * CAP;
    float ax = 0.f, ay = 0.f, az = 0.f, aw = 0.f;
    for (int j = 0; j < cnt; j++) {
        uint2 pe = b[j];  // lane-uniform -> broadcast
        float c = __uint_as_float(pe.y);
        uint2 hw = reinterpret_cast<const uint2*>(g_x_h + (size_t)pe.x * D)[lane];
        float2 f01 = __half22float2(*reinterpret_cast<__half2*>(&hw.x));
        float2 f23 = __half22float2(*reinterpret_cast<__half2*>(&hw.y));
        ax = fmaf(c, f01.x, ax);
        ay = fmaf(c, f01.y, ay);
        az = fmaf(c, f23.x, az);
        aw = fmaf(c, f23.y, aw);
    }

    if (cntr > CAP) {  // essentially-never: scan overflow list for this node
        int novf = g_ovf_cnt;
        if (novf > OVFCAP) novf = OVFCAP;
        for (int k = 0; k < novf; k++) {
            uint4 e = g_ovf[k];
            if (e.x == (unsigned)node) {
                float c = __uint_as_float(e.z);
                uint2 hw = reinterpret_cast<const uint2*>(g_x_h + (size_t)e.y * D)[lane];
                float2 f01 = __half22float2(*reinterpret_cast<__half2*>(&hw.x));
                float2 f23 = __half22float2(*reinterpret_cast<__half2*>(&hw.y));
                ax = fmaf(c, f01.x, ax);
                ay = fmaf(c, f01.y, ay);
                az = fmaf(c, f23.x, az);
                aw = fmaf(c, f23.y, aw);
            }
        }
    }

    float4 x0v = reinterpret_cast<const float4*>(x0 + (size_t)node * D)[lane];
    float4 o = make_float4(fmaxf(fmaf(EPS, x0v.x, ax), 0.f),
                           fmaxf(fmaf(EPS, x0v.y, ay), 0.f),
                           fmaxf(fmaf(EPS, x0v.z, az), 0.f),
                           fmaxf(fmaf(EPS, x0v.w, aw), 0.f));
    reinterpret_cast<float4*>(g_agg + (size_t)node * D)[lane] = o;
}

// ---------------------------------------------------------------------------
// Kernel 3: out = agg @ W^T + b via bf16x3 mma.m16n8k16, 2 CTAs/SM.
// (relu already applied by pull)
// ---------------------------------------------------------------------------
#define PITCH 68   // words per row (64 + 4 pad)

#define SM_WHI 0
#define SM_WLO (128 * PITCH)
#define SM_AHI (2 * 128 * PITCH)
#define SM_ALO (2 * 128 * PITCH + 64 * PITCH)
#define SM_WORDS (2 * 128 * PITCH + 2 * 64 * PITCH)

__device__ __forceinline__ void mma_bf16(float* d, const uint32_t* a, const uint32_t* b) {
    asm volatile(
        "mma.sync.aligned.m16n8k16.row.col.f32.bf16.bf16.f32 "
        "{%0,%1,%2,%3}, {%4,%5,%6,%7}, {%8,%9}, {%0,%1,%2,%3};"
        : "+f"(d[0]), "+f"(d[1]), "+f"(d[2]), "+f"(d[3])
        : "r"(a[0]), "r"(a[1]), "r"(a[2]), "r"(a[3]), "r"(b[0]), "r"(b[1]));
}

__global__ __launch_bounds__(256, 2)
void gemm_kernel(const float* __restrict__ bias,
                 float* __restrict__ out,
                 int N) {
    extern __shared__ uint32_t sm[];
    int tid = threadIdx.x;
    int lane = tid & 31;
    int wid = tid >> 5;
    int warpM = wid >> 2;
    int warpN = wid & 3;

    for (int i = tid; i < 128 * 16; i += 256) {
        int r = i >> 4;
        int c4 = i & 15;
        uint4 h = reinterpret_cast<const uint4*>(g_W_hi)[(size_t)r * 16 + c4];
        uint4 l = reinterpret_cast<const uint4*>(g_W_lo)[(size_t)r * 16 + c4];
        *reinterpret_cast<uint4*>(&sm[SM_WHI + r * PITCH + c4 * 4]) = h;
        *reinterpret_cast<uint4*>(&sm[SM_WLO + r * PITCH + c4 * 4]) = l;
    }

    float bv[4][2];
#pragma unroll
    for (int nt = 0; nt < 4; nt++) {
        int col = warpN * 32 + nt * 8 + (lane & 3) * 2;
        bv[nt][0] = bias[col];
        bv[nt][1] = bias[col + 1];
    }
    __syncthreads();

    int ntiles = (N + 63) >> 6;
    for (int t = blockIdx.x; t < ntiles; t += gridDim.x) {
        int m0 = t << 6;

        for (int i = tid; i < 64 * 32; i += 256) {
            int r = i >> 5;
            int c4 = i & 31;
            int row = m0 + r;
            float4 v;
            if (row < N)
                v = *reinterpret_cast<const float4*>(g_agg + (size_t)row * D + c4 * 4);
            else
                v = make_float4(0.f, 0.f, 0.f, 0.f);
            __nv_bfloat16 h0 = __float2bfloat16_rn(v.x);
            __nv_bfloat16 h1 = __float2bfloat16_rn(v.y);
            __nv_bfloat16 h2 = __float2bfloat16_rn(v.z);
            __nv_bfloat16 h3 = __float2bfloat16_rn(v.w);
            __nv_bfloat162 hp0 = __halves2bfloat162(h0, h1);
            __nv_bfloat162 hp1 = __halves2bfloat162(h2, h3);
            __nv_bfloat162 lp0 = __halves2bfloat162(
                __float2bfloat16_rn(v.x - __bfloat162float(h0)),
                __float2bfloat16_rn(v.y - __bfloat162float(h1)));
            __nv_bfloat162 lp1 = __halves2bfloat162(
                __float2bfloat16_rn(v.z - __bfloat162float(h2)),
                __float2bfloat16_rn(v.w - __bfloat162float(h3)));
            uint2 hw = make_uint2(*reinterpret_cast<uint32_t*>(&hp0),
                                  *reinterpret_cast<uint32_t*>(&hp1));
            uint2 lw = make_uint2(*reinterpret_cast<uint32_t*>(&lp0),
                                  *reinterpret_cast<uint32_t*>(&lp1));
            *reinterpret_cast<uint2*>(&sm[SM_AHI + r * PITCH + c4 * 2]) = hw;
            *reinterpret_cast<uint2*>(&sm[SM_ALO + r * PITCH + c4 * 2]) = lw;
        }
        __syncthreads();

        float acc[2][4][4];
#pragma unroll
        for (int mt = 0; mt < 2; mt++)
#pragma unroll
            for (int nt = 0; nt < 4; nt++)
#pragma unroll
                for (int i = 0; i < 4; i++) acc[mt][nt][i] = 0.f;

#pragma unroll
        for (int ks = 0; ks < 8; ks++) {
            int w0 = ks * 8 + (lane & 3);
            uint32_t ahi[2][4], alo[2][4];
#pragma unroll
            for (int mt = 0; mt < 2; mt++) {
                int r = warpM * 32 + mt * 16 + (lane >> 2);
                ahi[mt][0] = sm[SM_AHI + r * PITCH + w0];
                ahi[mt][1] = sm[SM_AHI + (r + 8) * PITCH + w0];
                ahi[mt][2] = sm[SM_AHI + r * PITCH + w0 + 4];
                ahi[mt][3] = sm[SM_AHI + (r + 8) * PITCH + w0 + 4];
                alo[mt][0] = sm[SM_ALO + r * PITCH + w0];
                alo[mt][1] = sm[SM_ALO + (r + 8) * PITCH + w0];
                alo[mt][2] = sm[SM_ALO + r * PITCH + w0 + 4];
                alo[mt][3] = sm[SM_ALO + (r + 8) * PITCH + w0 + 4];
            }
            uint32_t bhi[4][2], blo[4][2];
#pragma unroll
            for (int nt = 0; nt < 4; nt++) {
                int n = warpN * 32 + nt * 8 + (lane >> 2);
                bhi[nt][0] = sm[SM_WHI + n * PITCH + w0];
                bhi[nt][1] = sm[SM_WHI + n * PITCH + w0 + 4];
                blo[nt][0] = sm[SM_WLO + n * PITCH + w0];
                blo[nt][1] = sm[SM_WLO + n * PITCH + w0 + 4];
            }
#pragma unroll
            for (int mt = 0; mt < 2; mt++)
#pragma unroll
                for (int nt = 0; nt < 4; nt++) {
                    mma_bf16(acc[mt][nt], ahi[mt], blo[nt]);
                    mma_bf16(acc[mt][nt], alo[mt], bhi[nt]);
                    mma_bf16(acc[mt][nt], ahi[mt], bhi[nt]);
                }
        }

#pragma unroll
        for (int mt = 0; mt < 2; mt++) {
            int r0 = m0 + warpM * 32 + mt * 16 + (lane >> 2);
#pragma unroll
            for (int nt = 0; nt < 4; nt++) {
                int col = warpN * 32 + nt * 8 + (lane & 3) * 2;
                if (r0 < N) {
                    float2 v = make_float2(acc[mt][nt][0] + bv[nt][0],
                                           acc[mt][nt][1] + bv[nt][1]);
                    *reinterpret_cast<float2*>(out + (size_t)r0 * OUTD + col) = v;
                }
                if (r0 + 8 < N) {
                    float2 v = make_float2(acc[mt][nt][2] + bv[nt][0],
                                           acc[mt][nt][3] + bv[nt][1]);
                    *reinterpret_cast<float2*>(out + (size_t)(r0 + 8) * OUTD + col) = v;
                }
            }
        }
        __syncthreads();
    }
}

// ---------------------------------------------------------------------------
// Launch
// ---------------------------------------------------------------------------
extern "C" void kernel_launch(void* const* d_in, const int* in_sizes, int n_in,
                              void* d_out, int out_size) {
    const float* x      = (const float*)d_in[0];
    const float* x0     = (const float*)d_in[1];
    const float* ew     = (const float*)d_in[2];
    const float* att_l  = (const float*)d_in[3];
    const float* att_r  = (const float*)d_in[4];
    const float* W      = (const float*)d_in[5];
    const float* bias   = (const float*)d_in[6];
    const void*  ei     = (const void*)d_in[7];
    float* out = (float*)d_out;

    int N = in_sizes[1] / D;
    int E = in_sizes[2];

    static bool attr_set = false;
    if (!attr_set) {
        cudaFuncSetAttribute(gemm_kernel,
                             cudaFuncAttributeMaxDynamicSharedMemorySize,
                             SM_WORDS * 4);
        attr_set = true;
    }

    int nzero = (N + 255) / 256;
    prep_kernel<<<32 + nzero + 1, 256>>>(W, (const unsigned int*)ei, N, E, nzero);
    {
        int blocks = (N + 7) / 8;
        alpha_init_kernel<<<blocks, 256>>>(x, att_l, att_r, N);
    }
    fill_kernel<<<(E + 255) / 256, 256>>>(ei, ew, E);
    {
        int blocks = (N + 7) / 8;
        pull_kernel<<<blocks, 256>>>(x0, N);
    }
    gemm_kernel<<<296, 256, SM_WORDS * 4>>>(bias, out, N);
}

// round 10
// speedup vs baseline: 1.1652x; 1.1115x over previous
#include <cuda_runtime.h>
#include <cuda_bf16.h>
#include <cuda_fp16.h>
#include <cstdint>

#define D 128
#define OUTD 128
#define MAXN 100000
#define EPS 0.1f
#define CAP 48        // per-dst bucket capacity (avg in-degree 6.4)
#define OVFCAP 262144 // overflow list capacity (correctness fallback)

// Scratch (allocation-free rule: __device__ globals)
__device__ float   g_agg[(size_t)MAXN * D];   // relu(EPS*x0 + sum) after pull
__device__ __half  g_x_h[(size_t)MAXN * D];
__device__ float   g_alpha_l[MAXN];
__device__ float   g_alpha_r[MAXN];
__device__ int     g_is64;
__device__ uint32_t g_W_hi[128 * 64];   // bf16x2 packed, [n][k/2]
__device__ uint32_t g_W_lo[128 * 64];
__device__ int     g_cnt[MAXN];
__device__ uint2   g_bucket[(size_t)MAXN * CAP];  // (src, coeff bits)
__device__ int     g_ovf_cnt;
__device__ uint4   g_ovf[OVFCAP];                 // (dst, src, coeff bits, 0)

// ---------------------------------------------------------------------------
// Kernel P: fused prep. blocks [0,32): W -> bf16 hi/lo; [32, 32+NZ): zero cnt;
// last block: int64/int32 detect + zero overflow counter.
// ---------------------------------------------------------------------------
__global__ void prep_kernel(const float* __restrict__ W,
                            const unsigned int* __restrict__ ei_words,
                            int N, int E, int nzero) {
    int b = blockIdx.x;
    if (b < 32) {
        int idx = b * 256 + threadIdx.x;  // < 8192
        int n = idx >> 6, k2 = idx & 63;
        float w0 = W[n * D + 2 * k2];
        float w1 = W[n * D + 2 * k2 + 1];
        __nv_bfloat16 h0 = __float2bfloat16_rn(w0);
        __nv_bfloat16 h1 = __float2bfloat16_rn(w1);
        float l0 = w0 - __bfloat162float(h0);
        float l1 = w1 - __bfloat162float(h1);
        __nv_bfloat162 hp = __halves2bfloat162(h0, h1);
        __nv_bfloat162 lp = __halves2bfloat162(__float2bfloat16_rn(l0),
                                               __float2bfloat16_rn(l1));
        g_W_hi[idx] = *reinterpret_cast<uint32_t*>(&hp);
        g_W_lo[idx] = *reinterpret_cast<uint32_t*>(&lp);
    } else if (b < 32 + nzero) {
        int i = (b - 32) * 256 + threadIdx.x;
        if (i < N) g_cnt[i] = 0;
    } else {
        __shared__ int bad;
        if (threadIdx.x == 0) { bad = 0; g_ovf_cnt = 0; }
        __syncthreads();
        int nchk = E < 1024 ? E : 1024;
        for (int k = threadIdx.x; k < nchk; k += blockDim.x)
            if (ei_words[2 * k + 1] != 0u) bad = 1;
        __syncthreads();
        if (threadIdx.x == 0) g_is64 = bad ? 0 : 1;
    }
}

// ---------------------------------------------------------------------------
// Kernel 1: alpha logits + fp16 copy of x
// ---------------------------------------------------------------------------
__global__ void alpha_init_kernel(const float* __restrict__ x,
                                  const float* __restrict__ att_l,
                                  const float* __restrict__ att_r,
                                  int N) {
    int warp = (blockIdx.x * blockDim.x + threadIdx.x) >> 5;
    int lane = threadIdx.x & 31;
    if (warp >= N) return;

    float4 xv = reinterpret_cast<const float4*>(x + (size_t)warp * D)[lane];
    float4 al = reinterpret_cast<const float4*>(att_l)[lane];
    float4 ar = reinterpret_cast<const float4*>(att_r)[lane];

    float sl = xv.x * al.x + xv.y * al.y + xv.z * al.z + xv.w * al.w;
    float sr = xv.x * ar.x + xv.y * ar.y + xv.z * ar.z + xv.w * ar.w;
#pragma unroll
    for (int o = 16; o > 0; o >>= 1) {
        sl += __shfl_xor_sync(0xffffffffu, sl, o);
        sr += __shfl_xor_sync(0xffffffffu, sr, o);
    }
    if (lane == 0) {
        g_alpha_l[warp] = sl;
        g_alpha_r[warp] = sr;
    }

    __half2 h01 = __floats2half2_rn(xv.x, xv.y);
    __half2 h23 = __floats2half2_rn(xv.z, xv.w);
    uint2 hw = make_uint2(*reinterpret_cast<uint32_t*>(&h01),
                          *reinterpret_cast<uint32_t*>(&h23));
    reinterpret_cast<uint2*>(g_x_h + (size_t)warp * D)[lane] = hw;
}

// ---------------------------------------------------------------------------
// Kernel 2a: fill per-dst buckets with (src, coeff). Thread per edge.
// ---------------------------------------------------------------------------
__global__ void fill_kernel(const void* __restrict__ ei_raw,
                            const float* __restrict__ ew,
                            int E) {
    int e = blockIdx.x * blockDim.x + threadIdx.x;
    if (e >= E) return;

    int src, dst;
    if (g_is64) {
        const long long* ei = (const long long*)ei_raw;
        src = (int)ei[e];
        dst = (int)ei[(size_t)E + e];
    } else {
        const int* ei = (const int*)ei_raw;
        src = ei[e];
        dst = ei[(size_t)E + e];
    }
    float c = tanhf(g_alpha_l[src] + g_alpha_r[dst]) * ew[e];

    int slot = atomicAdd(&g_cnt[dst], 1);
    if (slot < CAP) {
        g_bucket[(size_t)dst * CAP + slot] = make_uint2((unsigned)src, __float_as_uint(c));
    } else {
        int o = atomicAdd(&g_ovf_cnt, 1);
        if (o < OVFCAP)
            g_ovf[o] = make_uint4((unsigned)dst, (unsigned)src, __float_as_uint(c), 0u);
    }
}

// ---------------------------------------------------------------------------
// Kernel 2b: pull. Warp per dst node; bucket processed in chunks of 4 with
// CLAMPED indices (always-valid loads, coeff zeroed for inactive slots) ->
// 4 independent entry loads + 4 independent gathers in flight, no shuffles.
// Plain float4 store of relu(EPS*x0 + sum).
// ---------------------------------------------------------------------------
__global__ void pull_kernel(const float* __restrict__ x0, int N) {
    int node = (blockIdx.x * blockDim.x + threadIdx.x) >> 5;
    int lane = threadIdx.x & 31;
    if (node >= N) return;

    // issue x0 load first: independent of everything below
    float4 x0v = reinterpret_cast<const float4*>(x0 + (size_t)node * D)[lane];

    int cntr = g_cnt[node];
    int cnt = cntr > CAP ? CAP : cntr;

    const uint2* b = g_bucket + (size_t)node * CAP;
    float ax = 0.f, ay = 0.f, az = 0.f, aw = 0.f;

    for (int j0 = 0; j0 < cnt; j0 += 4) {
        uint2 pe[4];
        uint2 hw[4];
        // 4 independent lane-uniform entry loads, index clamped to valid range
#pragma unroll
        for (int i = 0; i < 4; i++) {
            int jc = j0 + i;
            if (jc > cnt - 1) jc = cnt - 1;   // always valid (cnt >= 1 here)
            pe[i] = b[jc];
            if (j0 + i >= cnt) pe[i].y = 0u;  // zero coeff for inactive slot
        }
        // 4 independent row gathers
#pragma unroll
        for (int i = 0; i < 4; i++)
            hw[i] = reinterpret_cast<const uint2*>(g_x_h + (size_t)pe[i].x * D)[lane];
#pragma unroll
        for (int i = 0; i < 4; i++) {
            float c = __uint_as_float(pe[i].y);
            float2 f01 = __half22float2(*reinterpret_cast<__half2*>(&hw[i].x));
            float2 f23 = __half22float2(*reinterpret_cast<__half2*>(&hw[i].y));
            ax = fmaf(c, f01.x, ax);
            ay = fmaf(c, f01.y, ay);
            az = fmaf(c, f23.x, az);
            aw = fmaf(c, f23.y, aw);
        }
    }

    if (cntr > CAP) {  // essentially-never: scan overflow list for this node
        int novf = g_ovf_cnt;
        if (novf > OVFCAP) novf = OVFCAP;
        for (int k = 0; k < novf; k++) {
            uint4 e = g_ovf[k];
            if (e.x == (unsigned)node) {
                float c = __uint_as_float(e.z);
                uint2 hw = reinterpret_cast<const uint2*>(g_x_h + (size_t)e.y * D)[lane];
                float2 f01 = __half22float2(*reinterpret_cast<__half2*>(&hw.x));
                float2 f23 = __half22float2(*reinterpret_cast<__half2*>(&hw.y));
                ax = fmaf(c, f01.x, ax);
                ay = fmaf(c, f01.y, ay);
                az = fmaf(c, f23.x, az);
                aw = fmaf(c, f23.y, aw);
            }
        }
    }

    float4 o = make_float4(fmaxf(fmaf(EPS, x0v.x, ax), 0.f),
                           fmaxf(fmaf(EPS, x0v.y, ay), 0.f),
                           fmaxf(fmaf(EPS, x0v.z, az), 0.f),
                           fmaxf(fmaf(EPS, x0v.w, aw), 0.f));
    reinterpret_cast<float4*>(g_agg + (size_t)node * D)[lane] = o;
}

// ---------------------------------------------------------------------------
// Kernel 3: out = agg @ W^T + b via bf16x3 mma.m16n8k16, 2 CTAs/SM.
// ---------------------------------------------------------------------------
#define PITCH 68   // words per row (64 + 4 pad)

#define SM_WHI 0
#define SM_WLO (128 * PITCH)
#define SM_AHI (2 * 128 * PITCH)
#define SM_ALO (2 * 128 * PITCH + 64 * PITCH)
#define SM_WORDS (2 * 128 * PITCH + 2 * 64 * PITCH)

__device__ __forceinline__ void mma_bf16(float* d, const uint32_t* a, const uint32_t* b) {
    asm volatile(
        "mma.sync.aligned.m16n8k16.row.col.f32.bf16.bf16.f32 "
        "{%0,%1,%2,%3}, {%4,%5,%6,%7}, {%8,%9}, {%0,%1,%2,%3};"
        : "+f"(d[0]), "+f"(d[1]), "+f"(d[2]), "+f"(d[3])
        : "r"(a[0]), "r"(a[1]), "r"(a[2]), "r"(a[3]), "r"(b[0]), "r"(b[1]));
}

__global__ __launch_bounds__(256, 2)
void gemm_kernel(const float* __restrict__ bias,
                 float* __restrict__ out,
                 int N) {
    extern __shared__ uint32_t sm[];
    int tid = threadIdx.x;
    int lane = tid & 31;
    int wid = tid >> 5;
    int warpM = wid >> 2;
    int warpN = wid & 3;

    for (int i = tid; i < 128 * 16; i += 256) {
        int r = i >> 4;
        int c4 = i & 15;
        uint4 h = reinterpret_cast<const uint4*>(g_W_hi)[(size_t)r * 16 + c4];
        uint4 l = reinterpret_cast<const uint4*>(g_W_lo)[(size_t)r * 16 + c4];
        *reinterpret_cast<uint4*>(&sm[SM_WHI + r * PITCH + c4 * 4]) = h;
        *reinterpret_cast<uint4*>(&sm[SM_WLO + r * PITCH + c4 * 4]) = l;
    }

    float bv[4][2];
#pragma unroll
    for (int nt = 0; nt < 4; nt++) {
        int col = warpN * 32 + nt * 8 + (lane & 3) * 2;
        bv[nt][0] = bias[col];
        bv[nt][1] = bias[col + 1];
    }
    __syncthreads();

    int ntiles = (N + 63) >> 6;
    for (int t = blockIdx.x; t < ntiles; t += gridDim.x) {
        int m0 = t << 6;

        for (int i = tid; i < 64 * 32; i += 256) {
            int r = i >> 5;
            int c4 = i & 31;
            int row = m0 + r;
            float4 v;
            if (row < N)
                v = *reinterpret_cast<const float4*>(g_agg + (size_t)row * D + c4 * 4);
            else
                v = make_float4(0.f, 0.f, 0.f, 0.f);
            __nv_bfloat16 h0 = __float2bfloat16_rn(v.x);
            __nv_bfloat16 h1 = __float2bfloat16_rn(v.y);
            __nv_bfloat16 h2 = __float2bfloat16_rn(v.z);
            __nv_bfloat16 h3 = __float2bfloat16_rn(v.w);
            __nv_bfloat162 hp0 = __halves2bfloat162(h0, h1);
            __nv_bfloat162 hp1 = __halves2bfloat162(h2, h3);
            __nv_bfloat162 lp0 = __halves2bfloat162(
                __float2bfloat16_rn(v.x - __bfloat162float(h0)),
                __float2bfloat16_rn(v.y - __bfloat162float(h1)));
            __nv_bfloat162 lp1 = __halves2bfloat162(
                __float2bfloat16_rn(v.z - __bfloat162float(h2)),
                __float2bfloat16_rn(v.w - __bfloat162float(h3)));
            uint2 hw = make_uint2(*reinterpret_cast<uint32_t*>(&hp0),
                                  *reinterpret_cast<uint32_t*>(&hp1));
            uint2 lw = make_uint2(*reinterpret_cast<uint32_t*>(&lp0),
                                  *reinterpret_cast<uint32_t*>(&lp1));
            *reinterpret_cast<uint2*>(&sm[SM_AHI + r * PITCH + c4 * 2]) = hw;
            *reinterpret_cast<uint2*>(&sm[SM_ALO + r * PITCH + c4 * 2]) = lw;
        }
        __syncthreads();

        float acc[2][4][4];
#pragma unroll
        for (int mt = 0; mt < 2; mt++)
#pragma unroll
            for (int nt = 0; nt < 4; nt++)
#pragma unroll
                for (int i = 0; i < 4; i++) acc[mt][nt][i] = 0.f;

#pragma unroll
        for (int ks = 0; ks < 8; ks++) {
            int w0 = ks * 8 + (lane & 3);
            uint32_t ahi[2][4], alo[2][4];
#pragma unroll
            for (int mt = 0; mt < 2; mt++) {
                int r = warpM * 32 + mt * 16 + (lane >> 2);
                ahi[mt][0] = sm[SM_AHI + r * PITCH + w0];
                ahi[mt][1] = sm[SM_AHI + (r + 8) * PITCH + w0];
                ahi[mt][2] = sm[SM_AHI + r * PITCH + w0 + 4];
                ahi[mt][3] = sm[SM_AHI + (r + 8) * PITCH + w0 + 4];
                alo[mt][0] = sm[SM_ALO + r * PITCH + w0];
                alo[mt][1] = sm[SM_ALO + (r + 8) * PITCH + w0];
                alo[mt][2] = sm[SM_ALO + r * PITCH + w0 + 4];
                alo[mt][3] = sm[SM_ALO + (r + 8) * PITCH + w0 + 4];
            }
            uint32_t bhi[4][2], blo[4][2];
#pragma unroll
            for (int nt = 0; nt < 4; nt++) {
                int n = warpN * 32 + nt * 8 + (lane >> 2);
                bhi[nt][0] = sm[SM_WHI + n * PITCH + w0];
                bhi[nt][1] = sm[SM_WHI + n * PITCH + w0 + 4];
                blo[nt][0] = sm[SM_WLO + n * PITCH + w0];
                blo[nt][1] = sm[SM_WLO + n * PITCH + w0 + 4];
            }
#pragma unroll
            for (int mt = 0; mt < 2; mt++)
#pragma unroll
                for (int nt = 0; nt < 4; nt++) {
                    mma_bf16(acc[mt][nt], ahi[mt], blo[nt]);
                    mma_bf16(acc[mt][nt], alo[mt], bhi[nt]);
                    mma_bf16(acc[mt][nt], ahi[mt], bhi[nt]);
                }
        }

#pragma unroll
        for (int mt = 0; mt < 2; mt++) {
            int r0 = m0 + warpM * 32 + mt * 16 + (lane >> 2);
#pragma unroll
            for (int nt = 0; nt < 4; nt++) {
                int col = warpN * 32 + nt * 8 + (lane & 3) * 2;
                if (r0 < N) {
                    float2 v = make_float2(acc[mt][nt][0] + bv[nt][0],
                                           acc[mt][nt][1] + bv[nt][1]);
                    *reinterpret_cast<float2*>(out + (size_t)r0 * OUTD + col) = v;
                }
                if (r0 + 8 < N) {
                    float2 v = make_float2(acc[mt][nt][2] + bv[nt][0],
                                           acc[mt][nt][3] + bv[nt][1]);
                    *reinterpret_cast<float2*>(out + (size_t)(r0 + 8) * OUTD + col) = v;
                }
            }
        }
        __syncthreads();
    }
}

// ---------------------------------------------------------------------------
// Launch
// ---------------------------------------------------------------------------
extern "C" void kernel_launch(void* const* d_in, const int* in_sizes, int n_in,
                              void* d_out, int out_size) {
    const float* x      = (const float*)d_in[0];
    const float* x0     = (const float*)d_in[1];
    const float* ew     = (const float*)d_in[2];
    const float* att_l  = (const float*)d_in[3];
    const float* att_r  = (const float*)d_in[4];
    const float* W      = (const float*)d_in[5];
    const float* bias   = (const float*)d_in[6];
    const void*  ei     = (const void*)d_in[7];
    float* out = (float*)d_out;

    int N = in_sizes[1] / D;
    int E = in_sizes[2];

    static bool attr_set = false;
    if (!attr_set) {
        cudaFuncSetAttribute(gemm_kernel,
                             cudaFuncAttributeMaxDynamicSharedMemorySize,
                             SM_WORDS * 4);
        attr_set = true;
    }

    int nzero = (N + 255) / 256;
    prep_kernel<<<32 + nzero + 1, 256>>>(W, (const unsigned int*)ei, N, E, nzero);
    {
        int blocks = (N + 7) / 8;
        alpha_init_kernel<<<blocks, 256>>>(x, att_l, att_r, N);
    }
    fill_kernel<<<(E + 255) / 256, 256>>>(ei, ew, E);
    {
        int blocks = (N + 7) / 8;
        pull_kernel<<<blocks, 256>>>(x0, N);
    }
    gemm_kernel<<<296, 256, SM_WORDS * 4>>>(bias, out, N);
}